// round 12
// baseline (speedup 1.0000x reference)
#include <cuda_runtime.h>
#include <cuda_fp16.h>

#define N_NODES_MAX 50000
#define IN_C  128
#define HID_C 64
#define OUT_C 32

// ---------------- scratch (no allocations allowed) ----------------
// g_deg counts IN-EDGES only (self loop handled as +1 at use sites).
// Zero-initialized at module load; re-zeroed by k_decode at the end of every
// launch, so every execution starts from deg==0.
__device__ int   g_deg [N_NODES_MAX];
__device__ int   g_rowstart[N_NODES_MAX];
__device__ int   g_cur [N_NODES_MAX];
__device__ float g_dinv[N_NODES_MAX];
__device__ int   g_esrc[1600000];                              // CSR src lists (cap 2x E)
__device__ __align__(16) __half g_xw1h[N_NODES_MAX * HID_C];   // x @ W1 (fp16 storage)
__device__ __align__(16) float  g_hw2 [N_NODES_MAX * OUT_C];   // relu(h) @ W2
__device__ __align__(16) __half g_z16 [N_NODES_MAX * OUT_C];   // z (fp16, decode only)

// ---------------- helpers for tf32 mma ----------------
__device__ __forceinline__ unsigned int f32_to_tf32(float f) {
    unsigned int r;
    asm("cvt.rna.tf32.f32 %0, %1;" : "=r"(r) : "f"(f));
    return r;
}

// ---------------- GEMM1 body (tensor core, tf32): one 128x64 tile ----------------
// 8 warps; warp = 16 rows x 64 cols. KT=32 k-phases, pad-36 smem (conflict-free).
// Called by gemm-role blocks of the fused kernels. Block-local syncs only.
__device__ __forceinline__ void gemm1_tile(const float* __restrict__ x,
                                           const float* __restrict__ W1,
                                           int row0, int n) {
    __shared__ __align__(16) unsigned int sA[128 * 36];  // [row][k]
    __shared__ __align__(16) unsigned int sB[64 * 36];   // [col][k] (W1 transposed)

    const int tid = threadIdx.x;
    const int warp = tid >> 5, lane = tid & 31;
    const int g = lane >> 2, t = lane & 3;
    const int wrow = warp * 16;

    float c[8][4];
#pragma unroll
    for (int i = 0; i < 8; i++)
#pragma unroll
        for (int j = 0; j < 4; j++) c[i][j] = 0.f;

#pragma unroll
    for (int kt = 0; kt < 4; kt++) {
        // stage x tile (128 rows x 32 k) as tf32
        {
            int r = tid >> 3, f4 = tid & 7;
#pragma unroll
            for (int p = 0; p < 4; p++, r += 32) {
                int gr = row0 + r;
                float4 v = make_float4(0.f, 0.f, 0.f, 0.f);
                if (gr < n) v = *(const float4*)(x + (size_t)gr * IN_C + kt * 32 + f4 * 4);
                unsigned int* d = sA + r * 36 + f4 * 4;
                d[0] = f32_to_tf32(v.x);
                d[1] = f32_to_tf32(v.y);
                d[2] = f32_to_tf32(v.z);
                d[3] = f32_to_tf32(v.w);
            }
        }
        // stage W1 tile transposed: sB[col][k]
        for (int i = tid; i < 32 * 64; i += 256) {
            int k = i >> 6, cc = i & 63;
            sB[cc * 36 + k] = f32_to_tf32(W1[(size_t)(kt * 32 + k) * HID_C + cc]);
        }
        __syncthreads();

#pragma unroll
        for (int ks = 0; ks < 4; ks++) {
            int kk = ks * 8;
            unsigned int a0 = sA[(wrow + g) * 36 + kk + t];
            unsigned int a1 = sA[(wrow + g + 8) * 36 + kk + t];
            unsigned int a2 = sA[(wrow + g) * 36 + kk + t + 4];
            unsigned int a3 = sA[(wrow + g + 8) * 36 + kk + t + 4];
#pragma unroll
            for (int nt = 0; nt < 8; nt++) {
                unsigned int b0 = sB[(nt * 8 + g) * 36 + kk + t];
                unsigned int b1 = sB[(nt * 8 + g) * 36 + kk + t + 4];
                asm volatile(
                    "mma.sync.aligned.m16n8k8.row.col.f32.tf32.tf32.f32 "
                    "{%0,%1,%2,%3}, {%4,%5,%6,%7}, {%8,%9}, {%0,%1,%2,%3};"
                    : "+f"(c[nt][0]), "+f"(c[nt][1]), "+f"(c[nt][2]), "+f"(c[nt][3])
                    : "r"(a0), "r"(a1), "r"(a2), "r"(a3), "r"(b0), "r"(b1));
            }
        }
        __syncthreads();
    }

    int r0 = row0 + wrow + g;
    int r1 = r0 + 8;
#pragma unroll
    for (int nt = 0; nt < 8; nt++) {
        int col = nt * 8 + 2 * t;
        if (r0 < n) {
            __half2 p = __floats2half2_rn(c[nt][0], c[nt][1]);
            *(__half2*)(g_xw1h + (size_t)r0 * HID_C + col) = p;
        }
        if (r1 < n) {
            __half2 p = __floats2half2_rn(c[nt][2], c[nt][3]);
            *(__half2*)(g_xw1h + (size_t)r1 * HID_C + col) = p;
        }
    }
}

// ---------------- fused: degree histogram || gemm half 1 ----------------
// Blocks [0, nbE): atomic in-degree histogram. Blocks [nbE, nbE+nbg): gemm tiles.
__global__ __launch_bounds__(256) void k_deg_gemm(const int* __restrict__ dst, int E,
                                                  const float* __restrict__ x,
                                                  const float* __restrict__ W1,
                                                  int nbE, int n) {
    int bid = blockIdx.x;
    if (bid < nbE) {
        int e = bid * 256 + threadIdx.x;
        if (e < E) atomicAdd(&g_deg[dst[e]], 1);
    } else {
        gemm1_tile(x, W1, (bid - nbE) * 128, n);
    }
}

// ---------------- single-kernel scan: rowstart = exclusive-prefix(deg) ----------------
__global__ __launch_bounds__(256) void k_scan(int n) {
    __shared__ int swarp[8];
    __shared__ int soff[8];
    int bid = blockIdx.x;
    int tid = threadIdx.x;
    int lane = tid & 31, warp = tid >> 5;

    // block offset = sum deg[0 .. bid*256)
    int limit = bid * 256;
    int s = 0;
    for (int j = tid; j < limit; j += 256) s += g_deg[j];
#pragma unroll
    for (int o = 16; o > 0; o >>= 1) s += __shfl_down_sync(0xffffffffu, s, o);
    if (lane == 0) soff[warp] = s;
    __syncthreads();
    if (tid < 8) {
        int t = soff[tid];
#pragma unroll
        for (int o = 4; o > 0; o >>= 1) t += __shfl_down_sync(0xffu, t, o);
        if (tid == 0) soff[0] = t;
    }
    __syncthreads();
    int off = soff[0];

    int i = bid * 256 + tid;
    int deg = (i < n) ? g_deg[i] : 0;
    int incl = deg;
#pragma unroll
    for (int o = 1; o < 32; o <<= 1) {
        int t = __shfl_up_sync(0xffffffffu, incl, o);
        if (lane >= o) incl += t;
    }
    if (lane == 31) swarp[warp] = incl;
    __syncthreads();
    if (tid < 8) {
        int t = swarp[tid];
        int si = t;
#pragma unroll
        for (int o = 1; o < 8; o <<= 1) {
            int u = __shfl_up_sync(0xffu, si, o);
            if (tid >= o) si += u;
        }
        swarp[tid] = si - t;   // exclusive warp offsets
    }
    __syncthreads();
    if (i < n) {
        int rs = off + swarp[warp] + (incl - deg);
        g_rowstart[i] = rs;
        g_cur[i] = rs;
        g_dinv[i] = rsqrtf((float)(deg + 1));
    }
}

// ---------------- fused: CSR fill || gemm half 2 ----------------
__global__ __launch_bounds__(256) void k_fill_gemm(const int* __restrict__ src,
                                                   const int* __restrict__ dst, int E,
                                                   const float* __restrict__ x,
                                                   const float* __restrict__ W1,
                                                   int nbE, int rowbase, int n) {
    int bid = blockIdx.x;
    if (bid < nbE) {
        int e = bid * 256 + threadIdx.x;
        if (e < E) {
            int pos = atomicAdd(&g_cur[dst[e]], 1);
            g_esrc[pos] = src[e];
        }
    } else {
        gemm1_tile(x, W1, rowbase + (bid - nbE) * 128, n);
    }
}

// ---------------- fused: gather layer1 (+b1, relu) then @W2 -> g_hw2 ----------------
__global__ __launch_bounds__(256) void k_gather1_layer2(const float* __restrict__ b1,
                                                        const float* __restrict__ W2, int n) {
    __shared__ __align__(16) float sh[16 * 68];   // relu(agg1) rows, padded
    __shared__ float sW2[HID_C * OUT_C];          // sW2[k*32 + c]
    int tid = threadIdx.x;
    for (int i = tid; i < HID_C * OUT_C; i += 256) sW2[i] = W2[i];

    int grp = tid >> 4, l = tid & 15;             // node group, lane (4 dims = 8B fp16)
    int node = blockIdx.x * 16 + grp;
    if (node < n) {
        float dn = g_dinv[node];
        int beg = g_rowstart[node];
        int end = beg + g_deg[node];

        uint2 us = *(const uint2*)(g_xw1h + (size_t)node * HID_C + l * 4);
        float2 s0 = __half22float2(*(const __half2*)&us.x);
        float2 s1 = __half22float2(*(const __half2*)&us.y);
        float s = dn * dn;
        float4 bb = *(const float4*)(b1 + l * 4);
        float4 acc;
        acc.x = fmaf(s0.x, s, bb.x); acc.y = fmaf(s0.y, s, bb.y);
        acc.z = fmaf(s1.x, s, bb.z); acc.w = fmaf(s1.y, s, bb.w);

        int j = beg;
        for (; j + 1 < end; j += 2) {
            int n0 = g_esrc[j], n1 = g_esrc[j + 1];
            float w0 = g_dinv[n0] * dn, w1 = g_dinv[n1] * dn;
            uint2 u0 = *(const uint2*)(g_xw1h + (size_t)n0 * HID_C + l * 4);
            uint2 u1 = *(const uint2*)(g_xw1h + (size_t)n1 * HID_C + l * 4);
            float2 a0 = __half22float2(*(const __half2*)&u0.x);
            float2 a1 = __half22float2(*(const __half2*)&u0.y);
            float2 c0 = __half22float2(*(const __half2*)&u1.x);
            float2 c1 = __half22float2(*(const __half2*)&u1.y);
            acc.x = fmaf(a0.x, w0, acc.x); acc.y = fmaf(a0.y, w0, acc.y);
            acc.z = fmaf(a1.x, w0, acc.z); acc.w = fmaf(a1.y, w0, acc.w);
            acc.x = fmaf(c0.x, w1, acc.x); acc.y = fmaf(c0.y, w1, acc.y);
            acc.z = fmaf(c1.x, w1, acc.z); acc.w = fmaf(c1.y, w1, acc.w);
        }
        if (j < end) {
            int n0 = g_esrc[j];
            float w0 = g_dinv[n0] * dn;
            uint2 u0 = *(const uint2*)(g_xw1h + (size_t)n0 * HID_C + l * 4);
            float2 a0 = __half22float2(*(const __half2*)&u0.x);
            float2 a1 = __half22float2(*(const __half2*)&u0.y);
            acc.x = fmaf(a0.x, w0, acc.x); acc.y = fmaf(a0.y, w0, acc.y);
            acc.z = fmaf(a1.x, w0, acc.z); acc.w = fmaf(a1.y, w0, acc.w);
        }
        float* dsth = sh + grp * 68 + l * 4;
        dsth[0] = fmaxf(acc.x, 0.f);
        dsth[1] = fmaxf(acc.y, 0.f);
        dsth[2] = fmaxf(acc.z, 0.f);
        dsth[3] = fmaxf(acc.w, 0.f);
    }
    __syncthreads();

    int nd = tid >> 4, c = tid & 15;
    int gnode = blockIdx.x * 16 + nd;
    if (gnode >= n) return;
    const float* hrow = sh + nd * 68;
    float a0 = 0.f, a1 = 0.f;
#pragma unroll 8
    for (int k = 0; k < HID_C; k++) {
        float hk = hrow[k];
        a0 = fmaf(hk, sW2[k * OUT_C + c], a0);
        a1 = fmaf(hk, sW2[k * OUT_C + c + 16], a1);
    }
    g_hw2[(size_t)gnode * OUT_C + c]      = a0;
    g_hw2[(size_t)gnode * OUT_C + c + 16] = a1;
}

// ---------------- gather layer2 (+b2) -> z (fp16) ----------------
__global__ __launch_bounds__(256) void k_gather2(const float* __restrict__ b2, int n) {
    int tid = threadIdx.x;
    int grp = tid >> 3, l = tid & 7;
    int node = blockIdx.x * 32 + grp;
    if (node >= n) return;

    float dn = g_dinv[node];
    int beg = g_rowstart[node];
    int end = beg + g_deg[node];

    float4 acc = *(const float4*)(g_hw2 + (size_t)node * OUT_C + l * 4);
    float s = dn * dn;
    float4 bb = *(const float4*)(b2 + l * 4);
    acc.x = fmaf(acc.x, s, bb.x); acc.y = fmaf(acc.y, s, bb.y);
    acc.z = fmaf(acc.z, s, bb.z); acc.w = fmaf(acc.w, s, bb.w);

    int j = beg;
    for (; j + 1 < end; j += 2) {
        int s0 = g_esrc[j], s1 = g_esrc[j + 1];
        float w0 = g_dinv[s0] * dn, w1 = g_dinv[s1] * dn;
        float4 v0 = *(const float4*)(g_hw2 + (size_t)s0 * OUT_C + l * 4);
        float4 v1 = *(const float4*)(g_hw2 + (size_t)s1 * OUT_C + l * 4);
        acc.x = fmaf(v0.x, w0, acc.x); acc.y = fmaf(v0.y, w0, acc.y);
        acc.z = fmaf(v0.z, w0, acc.z); acc.w = fmaf(v0.w, w0, acc.w);
        acc.x = fmaf(v1.x, w1, acc.x); acc.y = fmaf(v1.y, w1, acc.y);
        acc.z = fmaf(v1.z, w1, acc.z); acc.w = fmaf(v1.w, w1, acc.w);
    }
    if (j < end) {
        int s0 = g_esrc[j];
        float w0 = g_dinv[s0] * dn;
        float4 v0 = *(const float4*)(g_hw2 + (size_t)s0 * OUT_C + l * 4);
        acc.x = fmaf(v0.x, w0, acc.x); acc.y = fmaf(v0.y, w0, acc.y);
        acc.z = fmaf(v0.z, w0, acc.z); acc.w = fmaf(v0.w, w0, acc.w);
    }
    __half2 p0 = __floats2half2_rn(acc.x, acc.y);
    __half2 p1 = __floats2half2_rn(acc.z, acc.w);
    uint2 u;
    u.x = *(const unsigned int*)&p0;
    u.y = *(const unsigned int*)&p1;
    *(uint2*)(g_z16 + (size_t)node * OUT_C + l * 4) = u;
}

// ---------------- decode: logits[e] = dot(z[a], z[b]) (fp16 z, fp32 math) ----------------
// Also resets g_deg to 0 for the next launch (keeps per-call state invariant).
__global__ __launch_bounds__(256) void k_decode(const int* __restrict__ de, int E,
                                                float* __restrict__ out, int n) {
    int g = blockIdx.x * blockDim.x + threadIdx.x;
    if (g < n) g_deg[g] = 0;   // restore deg==0 invariant for next call
    int e = g >> 2, t = g & 3;
    bool valid = (e < E);
    if (!valid) e = 0;
    int a = 0, b = 0;
    if (t == 0) { a = de[e]; b = de[E + e]; }
    a = __shfl_sync(0xffffffffu, a, 0, 4);
    b = __shfl_sync(0xffffffffu, b, 0, 4);
    uint4 ua = *(const uint4*)(g_z16 + (size_t)a * OUT_C + t * 8);
    uint4 ub = *(const uint4*)(g_z16 + (size_t)b * OUT_C + t * 8);
    float p = 0.f;
    const unsigned int* pa = &ua.x;
    const unsigned int* pb = &ub.x;
#pragma unroll
    for (int i = 0; i < 4; i++) {
        float2 fa = __half22float2(*(const __half2*)&pa[i]);
        float2 fb = __half22float2(*(const __half2*)&pb[i]);
        p = fmaf(fa.x, fb.x, p);
        p = fmaf(fa.y, fb.y, p);
    }
    p += __shfl_down_sync(0xffffffffu, p, 2, 4);
    p += __shfl_down_sync(0xffffffffu, p, 1, 4);
    if (valid && t == 0) out[e] = p;
}

// ---------------- launch ----------------
extern "C" void kernel_launch(void* const* d_in, const int* in_sizes, int n_in,
                              void* d_out, int out_size) {
    const float* x  = (const float*)d_in[0];
    const float* W1 = (const float*)d_in[1];
    const float* b1 = (const float*)d_in[2];
    const float* W2 = (const float*)d_in[3];
    const float* b2 = (const float*)d_in[4];
    const int*   ei = (const int*)d_in[5];
    const int*   de = (const int*)d_in[6];

    int N  = in_sizes[0] / IN_C;
    int E  = in_sizes[5] / 2;
    int Ed = in_sizes[6] / 2;
    const int* src = ei;
    const int* dst = ei + E;
    float* out = (float*)d_out;

    int nb  = (N + 255) / 256;
    int nbE = (E + 255) / 256;
    int nbg_total = (N + 127) / 128;
    int nbg1 = nbg_total / 2;            // gemm tiles fused with deg
    int nbg2 = nbg_total - nbg1;         // gemm tiles fused with fill
    int rowbase2 = nbg1 * 128;

    k_deg_gemm<<<nbE + nbg1, 256>>>(dst, E, x, W1, nbE, N);
    k_scan<<<nb, 256>>>(N);
    k_fill_gemm<<<nbE + nbg2, 256>>>(src, dst, E, x, W1, nbE, rowbase2, N);

    k_gather1_layer2<<<(N + 15) / 16, 256>>>(b1, W2, N);
    k_gather2<<<(N + 31) / 32, 256>>>(b2, N);

    long long thd = (long long)Ed * 4;
    k_decode<<<(unsigned)((thd + 255) / 256), 256>>>(de, Ed, out, N);
}